// round 4
// baseline (speedup 1.0000x reference)
#include <cuda_runtime.h>

#define Bn 8
#define Cn 24
#define Mn 960
#define Wn 15                  // 64-bit words per row (960/64)
#define ROWS (Bn*Mn)           // 7680

#define RB 24                  // output rows per block (960 % 24 == 0)
#define RT (RB + 22)           // packed rows incl. vertical halo = 46
#define NT 384                 // threads per block (12 warps)

// Single fused kernel: pack (ballot) -> hrode -> verode -> border -> float4 out.
// All intermediates live in shared memory; zero global scratch traffic.
__global__ void __launch_bounds__(NT) fused_kernel(const float* __restrict__ in,
                                                   float* __restrict__ out) {
    __shared__ unsigned long long sF[RT][Wn];        // frontier bits (r=0 plane)
    __shared__ unsigned long long sH[6][RT][Wn];     // hrode planes r=4,6,7,8,9,10
    __shared__ unsigned long long sE[RB + 2][Wn];    // eroded rows (+-1 halo)
    __shared__ unsigned long long sB[RB][Wn];        // border words

    const int t    = threadIdx.x;
    const int lane = t & 31;
    const int warp = t >> 5;
    const int r0   = blockIdx.x * RB;                // global row base (b*Mn + y0)
    const int b    = r0 / Mn;
    const int y0   = r0 - b * Mn;

    // ── Phase 0: pack frontier = (channel-1 == 0) for rows y0-11 .. y0+RB+10.
    // One warp per 64-px word: 2 coalesced loads + 2 ballots + lane0 STS.
    const float* chan = in + (size_t)(b * Cn + 1) * (Mn * Mn);
    for (int task = warp; task < RT * Wn; task += NT / 32) {
        int rr = task / Wn, w = task - rr * Wn;
        int y = y0 + rr - 11;
        unsigned long long word = 0ULL;
        if (y >= 0 && y < Mn) {
            const float* p = chan + (size_t)y * Mn + (w << 6) + lane;
            unsigned lo = __ballot_sync(0xffffffffu, p[0]  == 0.0f);
            unsigned hi = __ballot_sync(0xffffffffu, p[32] == 0.0f);
            word = ((unsigned long long)hi << 32) | lo;
        }
        if (lane == 0) sF[rr][w] = word;
    }
    __syncthreads();

    // ── Phase A: horizontal erosions (incremental window AND), smem -> smem.
    for (int task = t; task < RT * Wn; task += NT) {
        int rr = task / Wn, w = task - rr * Wn;
        unsigned long long c = sF[rr][w];
        unsigned long long l = (w > 0)      ? sF[rr][w - 1] : 0ULL;
        unsigned long long r = (w < Wn - 1) ? sF[rr][w + 1] : 0ULL;
        unsigned long long acc = c;
#pragma unroll
        for (int d = 1; d <= 10; d++) {
            acc &= ((c << d) | (l >> (64 - d))) & ((c >> d) | (r << (64 - d)));
            if (d == 4)       sH[0][rr][w] = acc;
            else if (d == 6)  sH[1][rr][w] = acc;
            else if (d == 7)  sH[2][rr][w] = acc;
            else if (d == 8)  sH[3][rr][w] = acc;
            else if (d == 9)  sH[4][rr][w] = acc;
            else if (d == 10) sH[5][rr][w] = acc;
        }
    }
    __syncthreads();

    // ── Phase B: vertical AND of the 21 disk row-terms -> eroded (+-1 halo).
    for (int task = t; task < (RB + 2) * Wn; task += NT) {
        int rr = task / Wn, w = task - rr * Wn;
        int y = y0 + rr - 1;
        unsigned long long e = 0ULL;
        if (y >= 10 && y <= Mn - 11) {
            int h = rr + 10;                         // smem hrode row of dy=0
            e  = sH[5][h][w];
            e &= sH[4][h - 1][w] & sH[4][h + 1][w];
            e &= sH[4][h - 2][w] & sH[4][h + 2][w];
            e &= sH[4][h - 3][w] & sH[4][h + 3][w];
            e &= sH[4][h - 4][w] & sH[4][h + 4][w];
            e &= sH[3][h - 5][w] & sH[3][h + 5][w];
            e &= sH[3][h - 6][w] & sH[3][h + 6][w];
            e &= sH[2][h - 7][w] & sH[2][h + 7][w];
            e &= sH[1][h - 8][w] & sH[1][h + 8][w];
            e &= sH[0][h - 9][w] & sH[0][h + 9][w];
            e &= sF[h - 10][w]   & sF[h + 10][w];
        }
        sE[rr][w] = e;
    }
    __syncthreads();

    // ── Phase C: border = dilate(e, cross) & ~e, word-parallel.
    for (int task = t; task < RB * Wn; task += NT) {
        int rr = task / Wn, w = task - rr * Wn;
        unsigned long long e  = sE[rr + 1][w];
        unsigned long long eu = sE[rr][w];
        unsigned long long ed = sE[rr + 2][w];
        unsigned long long l  = (w > 0)      ? sE[rr + 1][w - 1] : 0ULL;
        unsigned long long r  = (w < Wn - 1) ? sE[rr + 1][w + 1] : 0ULL;
        unsigned long long d = e | eu | ed | (e << 1) | (l >> 63) | (e >> 1) | (r << 63);
        sB[rr][w] = d & ~e;
    }
    __syncthreads();

    // ── Phase D: expand bits -> float4, fully coalesced stores.
    float4* o = (float4*)out + (size_t)r0 * (Mn / 4);
#pragma unroll
    for (int k = 0; k < (RB * (Mn / 4)) / NT; k++) {   // 15 iterations, exact
        int c = t + k * NT;                            // float4 chunk in tile
        int rr = c / (Mn / 4), cc = c - rr * (Mn / 4);
        unsigned long long bw = sB[rr][cc >> 4];
        unsigned nib = (unsigned)(bw >> ((cc & 15) << 2)) & 15u;
        o[c] = make_float4(nib & 1u ? 1.0f : 0.0f, nib & 2u ? 1.0f : 0.0f,
                           nib & 4u ? 1.0f : 0.0f, nib & 8u ? 1.0f : 0.0f);
    }
}

extern "C" void kernel_launch(void* const* d_in, const int* in_sizes, int n_in,
                              void* d_out, int out_size) {
    const float* map_features = (const float*)d_in[0];
    float* out = (float*)d_out;
    fused_kernel<<<ROWS / RB, NT>>>(map_features, out);
}

// round 5
// speedup vs baseline: 2.4449x; 2.4449x over previous
#include <cuda_runtime.h>

#define Bn 8
#define Cn 24
#define Mn 960
#define Wn 15                   // 64-bit words per row (960/64)
#define ROWS (Bn*Mn)            // 7680
#define NW (ROWS*Wn)            // 115200 words

typedef unsigned long long u64;

// Global bitmap planes: frontier (r=0) + 6 hrode planes r = 4,6,7,8,9,10.
__device__ u64 g_F[NW];
__device__ u64 g_P[6][NW];

// ── K1: pack + horizontal erosion (row-local, no halo, DRAM-streaming).
// One warp packs a full 960-px row: 30 independent loads (MLP=30) + 30 ballots,
// then thread-per-word hrode writes frontier + 6 planes to global.
#define PR 16                   // rows per block
__global__ void __launch_bounds__(256) pack_kernel(const float* __restrict__ in) {
    __shared__ u64 sF[PR][Wn];
    const int lane = threadIdx.x & 31;
    const int warp = threadIdx.x >> 5;
    const int row0 = blockIdx.x * PR;                 // global row = b*Mn + y

#pragma unroll
    for (int i = 0; i < PR / 8; i++) {                // 8 warps, 2 rows each
        int rr = warp + (i << 3);
        int row = row0 + rr;
        int b = row / Mn, y = row - b * Mn;
        const float* p = in + ((size_t)(b * Cn + 1) * Mn + y) * Mn + lane;
        float v[30];
#pragma unroll
        for (int j = 0; j < 30; j++) v[j] = p[j * 32];
        unsigned bb[30];
#pragma unroll
        for (int j = 0; j < 30; j++) bb[j] = __ballot_sync(0xffffffffu, v[j] == 0.0f);
        if (lane < Wn) {
            unsigned lo = 0, hi = 0;
#pragma unroll
            for (int k = 0; k < Wn; k++)
                if (lane == k) { lo = bb[2 * k]; hi = bb[2 * k + 1]; }
            sF[rr][lane] = ((u64)hi << 32) | lo;
        }
    }
    __syncthreads();

    int t = threadIdx.x;
    if (t < PR * Wn) {                                // 240 words
        int rr = t / Wn, w = t - rr * Wn;
        u64 c = sF[rr][w];
        u64 l = (w > 0)      ? sF[rr][w - 1] : 0ULL;
        u64 r = (w < Wn - 1) ? sF[rr][w + 1] : 0ULL;
        int i = (row0 + rr) * Wn + w;
        g_F[i] = c;
        u64 acc = c;
#pragma unroll
        for (int d = 1; d <= 10; d++) {
            acc &= ((c << d) | (l >> (64 - d))) & ((c >> d) | (r << (64 - d)));
            if (d == 4)       g_P[0][i] = acc;
            else if (d == 6)  g_P[1][i] = acc;
            else if (d == 7)  g_P[2][i] = acc;
            else if (d == 8)  g_P[3][i] = acc;
            else if (d == 9)  g_P[4][i] = acc;
            else if (d == 10) g_P[5][i] = acc;
        }
    }
}

// ── K2: vertical 21-term AND (global L2 reads) -> border -> float4 expand.
// Tiny smem (2.2 KB) so occupancy is thread-limited, not smem-limited.
#define RB 8                    // output rows per block; grid = 960
__global__ void __launch_bounds__(256) morph_kernel(float* __restrict__ out) {
    __shared__ u64 sE[RB + 2][Wn];
    __shared__ u64 sB[RB][Wn];
    const int t  = threadIdx.x;
    const int r0 = blockIdx.x * RB;
    const int b  = r0 / Mn;
    const int y0 = r0 - b * Mn;

    // Phase B: eroded rows y0-1 .. y0+RB (±1 halo for the cross dilation)
    if (t < (RB + 2) * Wn) {                          // 150 tasks
        int rr = t / Wn, w = t - rr * Wn;
        int y = y0 + rr - 1;
        u64 e = 0ULL;
        if (y >= 10 && y <= Mn - 11) {
            int i = (b * Mn + y) * Wn + w;
            e  = g_P[5][i];
            e &= g_P[4][i - 1*Wn] & g_P[4][i + 1*Wn];
            e &= g_P[4][i - 2*Wn] & g_P[4][i + 2*Wn];
            e &= g_P[4][i - 3*Wn] & g_P[4][i + 3*Wn];
            e &= g_P[4][i - 4*Wn] & g_P[4][i + 4*Wn];
            e &= g_P[3][i - 5*Wn] & g_P[3][i + 5*Wn];
            e &= g_P[3][i - 6*Wn] & g_P[3][i + 6*Wn];
            e &= g_P[2][i - 7*Wn] & g_P[2][i + 7*Wn];
            e &= g_P[1][i - 8*Wn] & g_P[1][i + 8*Wn];
            e &= g_P[0][i - 9*Wn] & g_P[0][i + 9*Wn];
            e &= g_F[i - 10*Wn]   & g_F[i + 10*Wn];
        }
        sE[rr][w] = e;
    }
    __syncthreads();

    // Phase C: border = dilate(e, cross) & ~e
    if (t < RB * Wn) {                                // 120 tasks
        int rr = t / Wn, w = t - rr * Wn;
        u64 e  = sE[rr + 1][w];
        u64 eu = sE[rr][w];
        u64 ed = sE[rr + 2][w];
        u64 l  = (w > 0)      ? sE[rr + 1][w - 1] : 0ULL;
        u64 r  = (w < Wn - 1) ? sE[rr + 1][w + 1] : 0ULL;
        u64 d = e | eu | ed | (e << 1) | (l >> 63) | (e >> 1) | (r << 63);
        sB[rr][w] = d & ~e;
    }
    __syncthreads();

    // Phase D: bits -> float4, coalesced stores (RB*240 = 1920 chunks)
    float4* o = (float4*)out + (size_t)r0 * (Mn / 4);
#pragma unroll
    for (int k = 0; k < 8; k++) {
        int c = t + (k << 8);
        if (c < RB * (Mn / 4)) {
            int rr = c / (Mn / 4), cc = c - rr * (Mn / 4);
            u64 bw = sB[rr][cc >> 4];
            unsigned nib = (unsigned)(bw >> ((cc & 15) << 2)) & 15u;
            o[c] = make_float4(nib & 1u ? 1.0f : 0.0f, nib & 2u ? 1.0f : 0.0f,
                               nib & 4u ? 1.0f : 0.0f, nib & 8u ? 1.0f : 0.0f);
        }
    }
}

extern "C" void kernel_launch(void* const* d_in, const int* in_sizes, int n_in,
                              void* d_out, int out_size) {
    const float* map_features = (const float*)d_in[0];
    float* out = (float*)d_out;
    pack_kernel<<<ROWS / PR, 256>>>(map_features);    // 480 blocks
    morph_kernel<<<ROWS / RB, 256>>>(out);            // 960 blocks
}